// round 2
// baseline (speedup 1.0000x reference)
#include <cuda_runtime.h>
#include <cuda_bf16.h>

// ODEFunc: per-point fused MLP forward + analytic gradient.
// Packed f32x2 math: 2 batch points per thread. Weights in shared memory,
// replicated into both halves of a 64-bit word -> one broadcast LDS.64 per
// packed FFMA2 operand. NPAIR=1 + launch_bounds(128,4) to keep regs <=128
// (R1 showed 255 regs -> 11.8% occupancy -> issue-starved at 46%).

using u64 = unsigned long long;

__device__ __forceinline__ u64 pk(float lo, float hi) {
    u64 r; asm("mov.b64 %0,{%1,%2};" : "=l"(r) : "f"(lo), "f"(hi)); return r;
}
__device__ __forceinline__ void upk(u64 v, float& lo, float& hi) {
    asm("mov.b64 {%0,%1},%2;" : "=f"(lo), "=f"(hi) : "l"(v));
}
__device__ __forceinline__ u64 fma2(u64 a, u64 b, u64 c) {
    u64 d; asm("fma.rn.f32x2 %0,%1,%2,%3;" : "=l"(d) : "l"(a), "l"(b), "l"(c)); return d;
}
__device__ __forceinline__ u64 mul2(u64 a, u64 b) {
    u64 d; asm("mul.rn.f32x2 %0,%1,%2;" : "=l"(d) : "l"(a), "l"(b)); return d;
}
__device__ __forceinline__ u64 neg2(u64 a) { return a ^ 0x8000000080000000ULL; }

#define ONE2 0x3F8000003F800000ULL
#define HALF2 0x3F0000003F000000ULL

__device__ __forceinline__ float tanh_fast(float x) {
    float r; asm("tanh.approx.f32 %0,%1;" : "=f"(r) : "f"(x)); return r;
}
__device__ __forceinline__ float exp_fast(float x) {
    float r; asm("ex2.approx.f32 %0,%1;" : "=f"(r) : "f"(x * 1.4426950408889634f)); return r;
}
__device__ __forceinline__ float sigmoid_fast(float x) {
    return fmaf(0.5f, tanh_fast(0.5f * x), 0.5f);
}
__device__ __forceinline__ u64 tanh2(u64 v) {
    float a, b; upk(v, a, b);
    return pk(tanh_fast(a), tanh_fast(b));
}
__device__ __forceinline__ u64 elu2(u64 v) {
    float a, b; upk(v, a, b);
    a = a > 0.f ? a : (exp_fast(a) - 1.f);
    b = b > 0.f ? b : (exp_fast(b) - 1.f);
    return pk(a, b);
}

__global__ void __launch_bounds__(128, 4)
odefunc_kernel(const float* __restrict__ x,
               const float* __restrict__ mW0, const float* __restrict__ mb0,
               const float* __restrict__ mW1, const float* __restrict__ mb1,
               const float* __restrict__ mW2, const float* __restrict__ mb2,
               const float* __restrict__ pW1, const float* __restrict__ pb1,
               const float* __restrict__ pW2, const float* __restrict__ pb2,
               const float* __restrict__ pW3, const float* __restrict__ pb3,
               float* __restrict__ out, int npairs)
{
    // ---- weights -> shared, replicated into both f32x2 halves ----
    __shared__ u64 wsm[342];
    {
        const float* srcs[12] = {mW0, mb0, mW1, mb1, mW2, mb2,
                                 pW1, pb1, pW2, pb2, pW3, pb3};
        const int offs[13] = {0, 16, 24, 88, 96, 128, 132, 164, 180, 308, 324, 340, 342};
        for (int idx = threadIdx.x; idx < 342; idx += blockDim.x) {
            int seg = 0;
            #pragma unroll
            for (int s2 = 0; s2 < 12; s2++)
                if (idx >= offs[s2 + 1]) seg = s2 + 1;
            float w = srcs[seg][idx - offs[seg]];
            wsm[idx] = pk(w, w);
        }
    }
    __syncthreads();

    const u64* W0  = wsm;         // 16 : [i*2+j]
    const u64* B0  = wsm + 16;    // 8
    const u64* W1  = wsm + 24;    // 64 : [i*8+j]
    const u64* B1  = wsm + 88;    // 8
    const u64* W2  = wsm + 96;    // 32 : [i*8+j]
    const u64* B2  = wsm + 128;   // 4
    const u64* PW1 = wsm + 132;   // 32 : [v*16+o*2+i]
    const u64* PB1 = wsm + 164;   // 16 : [v*8+o]
    const u64* PW2 = wsm + 180;   // 128: [v*64+q*8+p]
    const u64* PB2 = wsm + 308;   // 16 : [v*8+q]
    const u64* PW3 = wsm + 324;   // 16 : [v*8+p]
    const u64* PB3 = wsm + 340;   // 2  : [v]

    const long long pi = (long long)blockIdx.x * blockDim.x + threadIdx.x;
    if (pi >= npairs) return;

    u64 X0, X1;
    {
        float4 xx = reinterpret_cast<const float4*>(x)[pi];
        X0 = pk(xx.x, xx.z);   // coord 0 of point a, point b
        X1 = pk(xx.y, xx.w);   // coord 1
    }

    // ================= main net =================
    u64 m2v, magA, magD;
    {
        u64 h0[8];
        #pragma unroll
        for (int i = 0; i < 8; i++)
            h0[i] = elu2(fma2(X1, W0[i * 2 + 1], fma2(X0, W0[i * 2], B0[i])));

        u64 h1[8];
        #pragma unroll
        for (int i = 0; i < 8; i++) {
            u64 acc = B1[i];
            #pragma unroll
            for (int j = 0; j < 8; j++)
                acc = fma2(h0[j], W1[i * 8 + j], acc);
            h1[i] = elu2(acc);
        }

        u64 bb[4];
        #pragma unroll
        for (int i = 0; i < 4; i++) {
            u64 acc = B2[i];
            #pragma unroll
            for (int j = 0; j < 8; j++)
                acc = fma2(h1[j], W2[i * 8 + j], acc);
            bb[i] = acc;
        }
        m2v  = fma2(bb[0], bb[1], mul2(bb[2], bb[3]));
        magA = fma2(bb[0], bb[0], mul2(bb[2], bb[2]));
        magD = fma2(bb[1], bb[1], mul2(bb[3], bb[3]));
    }

    // ================= p nets (NV=2), forward + analytic backward =================
    u64 G0 = 0ULL, G1 = 0ULL;

    #pragma unroll
    for (int v = 0; v < 2; v++) {
        // f1 = tanh(x @ pW1^T + pb1)
        u64 f1[8];
        #pragma unroll
        for (int o = 0; o < 8; o++)
            f1[o] = tanh2(fma2(X1, PW1[v * 16 + o * 2 + 1],
                          fma2(X0, PW1[v * 16 + o * 2], PB1[v * 8 + o])));

        // f2 = tanh(f1 @ pW2^T + pb2)
        u64 f2[8];
        #pragma unroll
        for (int q = 0; q < 8; q++) {
            u64 acc = PB2[v * 8 + q];
            #pragma unroll
            for (int pp = 0; pp < 8; pp++)
                acc = fma2(f1[pp], PW2[v * 64 + q * 8 + pp], acc);
            f2[q] = tanh2(acc);
        }

        // z = f2 . pW3 + pb3 ; s = sigma(sigma(z)) ; ds = s(1-s)
        u64 DS;
        {
            u64 acc = PB3[v];
            #pragma unroll
            for (int pp = 0; pp < 8; pp++)
                acc = fma2(f2[pp], PW3[v * 8 + pp], acc);
            float za, zb; upk(acc, za, zb);
            float sa = sigmoid_fast(sigmoid_fast(za));
            float sb = sigmoid_fast(sigmoid_fast(zb));
            DS = pk(sa * (1.f - sa), sb * (1.f - sb));
        }

        // gq_q = ds * pW3_q * (1 - f2_q^2)   (overwrite f2 in place)
        #pragma unroll
        for (int q = 0; q < 8; q++) {
            u64 t2 = fma2(f2[q], neg2(f2[q]), ONE2);
            f2[q] = mul2(mul2(DS, PW3[v * 8 + q]), t2);
        }

        // gp_p = (sum_q gq_q * W2[q,p]) * (1 - f1_p^2) ; G += gp_p * pW1[p,:]
        #pragma unroll
        for (int pp = 0; pp < 8; pp++) {
            u64 acc = 0ULL;
            #pragma unroll
            for (int q = 0; q < 8; q++)
                acc = fma2(f2[q], PW2[v * 64 + q * 8 + pp], acc);
            u64 t1 = fma2(f1[pp], neg2(f1[pp]), ONE2);
            u64 gpv = mul2(acc, t1);
            G0 = fma2(gpv, PW1[v * 16 + pp * 2], G0);
            G1 = fma2(gpv, PW1[v * 16 + pp * 2 + 1], G1);
        }
    }

    // out0 = 0.5*(magA*G0 + m2*G1); out1 = 0.5*(m2*G0 + magD*G1)
    u64 o0 = mul2(HALF2, fma2(magA, G0, mul2(m2v, G1)));
    u64 o1 = mul2(HALF2, fma2(m2v, G0, mul2(magD, G1)));
    float a0, b0c, a1, b1c;
    upk(o0, a0, b0c);
    upk(o1, a1, b1c);
    reinterpret_cast<float4*>(out)[pi] = make_float4(a0, a1, b0c, b1c);
}

extern "C" void kernel_launch(void* const* d_in, const int* in_sizes, int n_in,
                              void* d_out, int out_size)
{
    // d_in: 0 t, 1 x, 2 mW0, 3 mb0, 4 mW1, 5 mb1, 6 mW2, 7 mb2,
    //       8 pW1, 9 pb1, 10 pW2, 11 pb2, 12 pW3, 13 pb3
    const float* x   = (const float*)d_in[1];
    const float* mW0 = (const float*)d_in[2];
    const float* mb0 = (const float*)d_in[3];
    const float* mW1 = (const float*)d_in[4];
    const float* mb1 = (const float*)d_in[5];
    const float* mW2 = (const float*)d_in[6];
    const float* mb2 = (const float*)d_in[7];
    const float* pW1 = (const float*)d_in[8];
    const float* pb1 = (const float*)d_in[9];
    const float* pW2 = (const float*)d_in[10];
    const float* pb2 = (const float*)d_in[11];
    const float* pW3 = (const float*)d_in[12];
    const float* pb3 = (const float*)d_in[13];

    int B = in_sizes[1] / 2;       // x is (B, 2)
    int npairs = B / 2;            // B = 2^21, even
    int threads = 128;
    int blocks = (npairs + threads - 1) / threads;

    odefunc_kernel<<<blocks, threads>>>(x, mW0, mb0, mW1, mb1, mW2, mb2,
                                        pW1, pb1, pW2, pb2, pW3, pb3,
                                        (float*)d_out, npairs);
}

// round 3
// speedup vs baseline: 1.0598x; 1.0598x over previous
#include <cuda_runtime.h>
#include <cuda_bf16.h>

// ODEFunc: per-point fused MLP forward + analytic gradient.
// f32x2 packed math (2 points/lane-pair), NPAIR=2 pairs/thread so each
// broadcast LDS.64 weight feeds 2 FFMA2s. Split accumulators double the
// dependent-chain ILP. 64-thread blocks + launch_bounds(64,5) -> 204-reg
// budget, 10 warps/SM (R1: 255 regs/8 warps = latency-bound; R2: 128-reg
// cap = spill catastrophe).

using u64 = unsigned long long;

__device__ __forceinline__ u64 pk(float lo, float hi) {
    u64 r; asm("mov.b64 %0,{%1,%2};" : "=l"(r) : "f"(lo), "f"(hi)); return r;
}
__device__ __forceinline__ void upk(u64 v, float& lo, float& hi) {
    asm("mov.b64 {%0,%1},%2;" : "=f"(lo), "=f"(hi) : "l"(v));
}
__device__ __forceinline__ u64 fma2(u64 a, u64 b, u64 c) {
    u64 d; asm("fma.rn.f32x2 %0,%1,%2,%3;" : "=l"(d) : "l"(a), "l"(b), "l"(c)); return d;
}
__device__ __forceinline__ u64 mul2(u64 a, u64 b) {
    u64 d; asm("mul.rn.f32x2 %0,%1,%2;" : "=l"(d) : "l"(a), "l"(b)); return d;
}
__device__ __forceinline__ u64 add2(u64 a, u64 b) {
    u64 d; asm("add.rn.f32x2 %0,%1,%2;" : "=l"(d) : "l"(a), "l"(b)); return d;
}
__device__ __forceinline__ u64 neg2(u64 a) { return a ^ 0x8000000080000000ULL; }

#define ONE2 0x3F8000003F800000ULL
#define HALF2 0x3F0000003F000000ULL

__device__ __forceinline__ float tanh_fast(float x) {
    float r; asm("tanh.approx.f32 %0,%1;" : "=f"(r) : "f"(x)); return r;
}
__device__ __forceinline__ float exp_fast(float x) {
    float r; asm("ex2.approx.f32 %0,%1;" : "=f"(r) : "f"(x * 1.4426950408889634f)); return r;
}
__device__ __forceinline__ float sigmoid_fast(float x) {
    return fmaf(0.5f, tanh_fast(0.5f * x), 0.5f);
}
__device__ __forceinline__ u64 tanh2(u64 v) {
    float a, b; upk(v, a, b);
    return pk(tanh_fast(a), tanh_fast(b));
}
__device__ __forceinline__ u64 elu2(u64 v) {
    float a, b; upk(v, a, b);
    a = a > 0.f ? a : (exp_fast(a) - 1.f);
    b = b > 0.f ? b : (exp_fast(b) - 1.f);
    return pk(a, b);
}

#define NPAIR 2

__global__ void __launch_bounds__(64, 5)
odefunc_kernel(const float* __restrict__ x,
               const float* __restrict__ mW0, const float* __restrict__ mb0,
               const float* __restrict__ mW1, const float* __restrict__ mb1,
               const float* __restrict__ mW2, const float* __restrict__ mb2,
               const float* __restrict__ pW1, const float* __restrict__ pb1,
               const float* __restrict__ pW2, const float* __restrict__ pb2,
               const float* __restrict__ pW3, const float* __restrict__ pb3,
               float* __restrict__ out, int npairs)
{
    // ---- weights -> shared, replicated into both f32x2 halves ----
    __shared__ u64 wsm[342];
    {
        const float* srcs[12] = {mW0, mb0, mW1, mb1, mW2, mb2,
                                 pW1, pb1, pW2, pb2, pW3, pb3};
        const int offs[13] = {0, 16, 24, 88, 96, 128, 132, 164, 180, 308, 324, 340, 342};
        for (int idx = threadIdx.x; idx < 342; idx += blockDim.x) {
            int seg = 0;
            #pragma unroll
            for (int s2 = 0; s2 < 12; s2++)
                if (idx >= offs[s2 + 1]) seg = s2 + 1;
            float w = srcs[seg][idx - offs[seg]];
            wsm[idx] = pk(w, w);
        }
    }
    __syncthreads();

    const u64* W0  = wsm;         // 16 : [i*2+j]
    const u64* B0  = wsm + 16;    // 8
    const u64* W1  = wsm + 24;    // 64 : [i*8+j]
    const u64* B1  = wsm + 88;    // 8
    const u64* W2  = wsm + 96;    // 32 : [i*8+j]
    const u64* B2  = wsm + 128;   // 4
    const u64* PW1 = wsm + 132;   // 32 : [v*16+o*2+i]
    const u64* PB1 = wsm + 164;   // 16 : [v*8+o]
    const u64* PW2 = wsm + 180;   // 128: [v*64+q*8+p]
    const u64* PB2 = wsm + 308;   // 16 : [v*8+q]
    const u64* PW3 = wsm + 324;   // 16 : [v*8+p]
    const u64* PB3 = wsm + 340;   // 2  : [v]

    const long long base   = (long long)blockIdx.x * blockDim.x + threadIdx.x;
    const long long stride = (long long)gridDim.x * blockDim.x;

    long long pi[NPAIR];
    bool valid[NPAIR];
    u64 X0[NPAIR], X1[NPAIR];
    #pragma unroll
    for (int p = 0; p < NPAIR; p++) {
        pi[p] = base + (long long)p * stride;
        valid[p] = pi[p] < npairs;
        if (valid[p]) {
            float4 xx = reinterpret_cast<const float4*>(x)[pi[p]];
            X0[p] = pk(xx.x, xx.z);
            X1[p] = pk(xx.y, xx.w);
        } else {
            X0[p] = 0ULL; X1[p] = 0ULL;
        }
    }

    // ================= main net =================
    u64 m2v[NPAIR], magA[NPAIR], magD[NPAIR];
    {
        u64 h0[NPAIR][8];
        #pragma unroll
        for (int i = 0; i < 8; i++) {
            u64 w0 = W0[i * 2], w1 = W0[i * 2 + 1], b = B0[i];
            #pragma unroll
            for (int p = 0; p < NPAIR; p++)
                h0[p][i] = elu2(fma2(X1[p], w1, fma2(X0[p], w0, b)));
        }
        u64 h1[NPAIR][8];
        #pragma unroll
        for (int i = 0; i < 8; i++) {
            u64 a0[NPAIR], a1[NPAIR];
            u64 b = B1[i];
            #pragma unroll
            for (int p = 0; p < NPAIR; p++) { a0[p] = b; a1[p] = 0ULL; }
            #pragma unroll
            for (int j = 0; j < 8; j += 2) {
                u64 we = W1[i * 8 + j], wo = W1[i * 8 + j + 1];
                #pragma unroll
                for (int p = 0; p < NPAIR; p++) {
                    a0[p] = fma2(h0[p][j],     we, a0[p]);
                    a1[p] = fma2(h0[p][j + 1], wo, a1[p]);
                }
            }
            #pragma unroll
            for (int p = 0; p < NPAIR; p++) h1[p][i] = elu2(add2(a0[p], a1[p]));
        }
        u64 bb[NPAIR][4];
        #pragma unroll
        for (int i = 0; i < 4; i++) {
            u64 a0[NPAIR], a1[NPAIR];
            u64 b = B2[i];
            #pragma unroll
            for (int p = 0; p < NPAIR; p++) { a0[p] = b; a1[p] = 0ULL; }
            #pragma unroll
            for (int j = 0; j < 8; j += 2) {
                u64 we = W2[i * 8 + j], wo = W2[i * 8 + j + 1];
                #pragma unroll
                for (int p = 0; p < NPAIR; p++) {
                    a0[p] = fma2(h1[p][j],     we, a0[p]);
                    a1[p] = fma2(h1[p][j + 1], wo, a1[p]);
                }
            }
            #pragma unroll
            for (int p = 0; p < NPAIR; p++) bb[p][i] = add2(a0[p], a1[p]);
        }
        #pragma unroll
        for (int p = 0; p < NPAIR; p++) {
            m2v[p]  = fma2(bb[p][0], bb[p][1], mul2(bb[p][2], bb[p][3]));
            magA[p] = fma2(bb[p][0], bb[p][0], mul2(bb[p][2], bb[p][2]));
            magD[p] = fma2(bb[p][1], bb[p][1], mul2(bb[p][3], bb[p][3]));
        }
    }

    // ================= p nets (NV=2), forward + analytic backward =================
    u64 G0[NPAIR], G1[NPAIR];
    #pragma unroll
    for (int p = 0; p < NPAIR; p++) { G0[p] = 0ULL; G1[p] = 0ULL; }

    #pragma unroll
    for (int v = 0; v < 2; v++) {
        u64 f1[NPAIR][8];
        #pragma unroll
        for (int o = 0; o < 8; o++) {
            u64 w0 = PW1[v * 16 + o * 2], w1 = PW1[v * 16 + o * 2 + 1], b = PB1[v * 8 + o];
            #pragma unroll
            for (int p = 0; p < NPAIR; p++)
                f1[p][o] = tanh2(fma2(X1[p], w1, fma2(X0[p], w0, b)));
        }
        u64 f2[NPAIR][8];
        #pragma unroll
        for (int q = 0; q < 8; q++) {
            u64 a0[NPAIR], a1[NPAIR];
            u64 b = PB2[v * 8 + q];
            #pragma unroll
            for (int p = 0; p < NPAIR; p++) { a0[p] = b; a1[p] = 0ULL; }
            #pragma unroll
            for (int pp = 0; pp < 8; pp += 2) {
                u64 we = PW2[v * 64 + q * 8 + pp], wo = PW2[v * 64 + q * 8 + pp + 1];
                #pragma unroll
                for (int p = 0; p < NPAIR; p++) {
                    a0[p] = fma2(f1[p][pp],     we, a0[p]);
                    a1[p] = fma2(f1[p][pp + 1], wo, a1[p]);
                }
            }
            #pragma unroll
            for (int p = 0; p < NPAIR; p++) f2[p][q] = tanh2(add2(a0[p], a1[p]));
        }
        // z = f2 . pW3 + pb3 ; s = sigma(sigma(z)) ; ds = s(1-s)
        u64 DS[NPAIR];
        {
            u64 a0[NPAIR], a1[NPAIR];
            u64 b = PB3[v];
            #pragma unroll
            for (int p = 0; p < NPAIR; p++) { a0[p] = b; a1[p] = 0ULL; }
            #pragma unroll
            for (int pp = 0; pp < 8; pp += 2) {
                u64 we = PW3[v * 8 + pp], wo = PW3[v * 8 + pp + 1];
                #pragma unroll
                for (int p = 0; p < NPAIR; p++) {
                    a0[p] = fma2(f2[p][pp],     we, a0[p]);
                    a1[p] = fma2(f2[p][pp + 1], wo, a1[p]);
                }
            }
            #pragma unroll
            for (int p = 0; p < NPAIR; p++) {
                float za, zb; upk(add2(a0[p], a1[p]), za, zb);
                float sa = sigmoid_fast(sigmoid_fast(za));
                float sb = sigmoid_fast(sigmoid_fast(zb));
                DS[p] = pk(sa * (1.f - sa), sb * (1.f - sb));
            }
        }
        // gq_q = ds * pW3_q * (1 - f2_q^2)  (overwrite f2)
        #pragma unroll
        for (int q = 0; q < 8; q++) {
            u64 w3 = PW3[v * 8 + q];
            #pragma unroll
            for (int p = 0; p < NPAIR; p++) {
                u64 t2 = fma2(f2[p][q], neg2(f2[p][q]), ONE2);
                f2[p][q] = mul2(mul2(DS[p], w3), t2);
            }
        }
        // gp_p = (sum_q gq_q * W2[q,p]) * (1 - f1_p^2) ; G += gp_p * pW1[p,:]
        #pragma unroll
        for (int pp = 0; pp < 8; pp++) {
            u64 a0[NPAIR], a1[NPAIR];
            #pragma unroll
            for (int p = 0; p < NPAIR; p++) { a0[p] = 0ULL; a1[p] = 0ULL; }
            #pragma unroll
            for (int q = 0; q < 8; q += 2) {
                u64 we = PW2[v * 64 + q * 8 + pp], wo = PW2[v * 64 + (q + 1) * 8 + pp];
                #pragma unroll
                for (int p = 0; p < NPAIR; p++) {
                    a0[p] = fma2(f2[p][q],     we, a0[p]);
                    a1[p] = fma2(f2[p][q + 1], wo, a1[p]);
                }
            }
            u64 w0 = PW1[v * 16 + pp * 2], w1 = PW1[v * 16 + pp * 2 + 1];
            #pragma unroll
            for (int p = 0; p < NPAIR; p++) {
                u64 t1 = fma2(f1[p][pp], neg2(f1[p][pp]), ONE2);
                u64 gpv = mul2(add2(a0[p], a1[p]), t1);
                G0[p] = fma2(gpv, w0, G0[p]);
                G1[p] = fma2(gpv, w1, G1[p]);
            }
        }
    }

    // out0 = 0.5*(magA*G0 + m2*G1); out1 = 0.5*(m2*G0 + magD*G1)
    #pragma unroll
    for (int p = 0; p < NPAIR; p++) {
        if (!valid[p]) continue;
        u64 o0 = mul2(HALF2, fma2(magA[p], G0[p], mul2(m2v[p], G1[p])));
        u64 o1 = mul2(HALF2, fma2(m2v[p], G0[p], mul2(magD[p], G1[p])));
        float a0, b0c, a1, b1c;
        upk(o0, a0, b0c);
        upk(o1, a1, b1c);
        reinterpret_cast<float4*>(out)[pi[p]] = make_float4(a0, a1, b0c, b1c);
    }
}

extern "C" void kernel_launch(void* const* d_in, const int* in_sizes, int n_in,
                              void* d_out, int out_size)
{
    const float* x   = (const float*)d_in[1];
    const float* mW0 = (const float*)d_in[2];
    const float* mb0 = (const float*)d_in[3];
    const float* mW1 = (const float*)d_in[4];
    const float* mb1 = (const float*)d_in[5];
    const float* mW2 = (const float*)d_in[6];
    const float* mb2 = (const float*)d_in[7];
    const float* pW1 = (const float*)d_in[8];
    const float* pb1 = (const float*)d_in[9];
    const float* pW2 = (const float*)d_in[10];
    const float* pb2 = (const float*)d_in[11];
    const float* pW3 = (const float*)d_in[12];
    const float* pb3 = (const float*)d_in[13];

    int B = in_sizes[1] / 2;       // x is (B, 2)
    int npairs = B / 2;
    int threads = 64;
    long long tot_threads = (npairs + NPAIR - 1) / NPAIR;
    int blocks = (int)((tot_threads + threads - 1) / threads);

    odefunc_kernel<<<blocks, threads>>>(x, mW0, mb0, mW1, mb1, mW2, mb2,
                                        pW1, pb1, pW2, pb2, pW3, pb3,
                                        (float*)d_out, npairs);
}

// round 4
// speedup vs baseline: 1.3186x; 1.2442x over previous
#include <cuda_runtime.h>
#include <cuda_bf16.h>

// ODEFunc: per-point fused MLP forward + analytic gradient.
// f32x2 packed math (2 batch points per thread). Weights in shared memory,
// replicated into both f32x2 halves -> one broadcast LDS.64 per FFMA2 operand.
// NPAIR=1 + launch_bounds(128,3): ~170-reg budget fits the ~120-reg live
// state without spill (R2: 128-reg cap spilled; R3: NPAIR=2 at 168 spilled;
// R1: NPAIR=2 at 255 = no spill but only 8 warps/SM, issue 46%).
// Backward uses (f^2-1) instead of (1-f^2): the two sign flips cancel,
// removing all 64-bit XORs from the hot path.

using u64 = unsigned long long;

__device__ __forceinline__ u64 pk(float lo, float hi) {
    u64 r; asm("mov.b64 %0,{%1,%2};" : "=l"(r) : "f"(lo), "f"(hi)); return r;
}
__device__ __forceinline__ void upk(u64 v, float& lo, float& hi) {
    asm("mov.b64 {%0,%1},%2;" : "=f"(lo), "=f"(hi) : "l"(v));
}
__device__ __forceinline__ u64 fma2(u64 a, u64 b, u64 c) {
    u64 d; asm("fma.rn.f32x2 %0,%1,%2,%3;" : "=l"(d) : "l"(a), "l"(b), "l"(c)); return d;
}
__device__ __forceinline__ u64 mul2(u64 a, u64 b) {
    u64 d; asm("mul.rn.f32x2 %0,%1,%2;" : "=l"(d) : "l"(a), "l"(b)); return d;
}
__device__ __forceinline__ u64 add2(u64 a, u64 b) {
    u64 d; asm("add.rn.f32x2 %0,%1,%2;" : "=l"(d) : "l"(a), "l"(b)); return d;
}

#define MONE2 0xBF800000BF800000ULL  // (-1.0f, -1.0f)
#define HALF2 0x3F0000003F000000ULL  // ( 0.5f,  0.5f)

__device__ __forceinline__ float tanh_fast(float x) {
    float r; asm("tanh.approx.f32 %0,%1;" : "=f"(r) : "f"(x)); return r;
}
__device__ __forceinline__ float exp_fast(float x) {
    float r; asm("ex2.approx.f32 %0,%1;" : "=f"(r) : "f"(x * 1.4426950408889634f)); return r;
}
__device__ __forceinline__ float sigmoid_fast(float x) {
    return fmaf(0.5f, tanh_fast(0.5f * x), 0.5f);
}
__device__ __forceinline__ u64 tanh2(u64 v) {
    float a, b; upk(v, a, b);
    return pk(tanh_fast(a), tanh_fast(b));
}
__device__ __forceinline__ u64 elu2(u64 v) {
    float a, b; upk(v, a, b);
    a = a > 0.f ? a : (exp_fast(a) - 1.f);
    b = b > 0.f ? b : (exp_fast(b) - 1.f);
    return pk(a, b);
}

__global__ void __launch_bounds__(128, 3)
odefunc_kernel(const float* __restrict__ x,
               const float* __restrict__ mW0, const float* __restrict__ mb0,
               const float* __restrict__ mW1, const float* __restrict__ mb1,
               const float* __restrict__ mW2, const float* __restrict__ mb2,
               const float* __restrict__ pW1, const float* __restrict__ pb1,
               const float* __restrict__ pW2, const float* __restrict__ pb2,
               const float* __restrict__ pW3, const float* __restrict__ pb3,
               float* __restrict__ out, int npairs)
{
    // ---- weights -> shared, replicated into both f32x2 halves ----
    __shared__ u64 wsm[342];
    {
        const float* srcs[12] = {mW0, mb0, mW1, mb1, mW2, mb2,
                                 pW1, pb1, pW2, pb2, pW3, pb3};
        const int offs[13] = {0, 16, 24, 88, 96, 128, 132, 164, 180, 308, 324, 340, 342};
        for (int idx = threadIdx.x; idx < 342; idx += blockDim.x) {
            int seg = 0;
            #pragma unroll
            for (int s2 = 0; s2 < 12; s2++)
                if (idx >= offs[s2 + 1]) seg = s2 + 1;
            float w = srcs[seg][idx - offs[seg]];
            wsm[idx] = pk(w, w);
        }
    }
    __syncthreads();

    const u64* W0  = wsm;         // 16 : [i*2+j]
    const u64* B0  = wsm + 16;    // 8
    const u64* W1  = wsm + 24;    // 64 : [i*8+j]
    const u64* B1  = wsm + 88;    // 8
    const u64* W2  = wsm + 96;    // 32 : [i*8+j]
    const u64* B2  = wsm + 128;   // 4
    const u64* PW1 = wsm + 132;   // 32 : [v*16+o*2+i]
    const u64* PB1 = wsm + 164;   // 16 : [v*8+o]
    const u64* PW2 = wsm + 180;   // 128: [v*64+q*8+p]
    const u64* PB2 = wsm + 308;   // 16 : [v*8+q]
    const u64* PW3 = wsm + 324;   // 16 : [v*8+p]
    const u64* PB3 = wsm + 340;   // 2  : [v]

    const long long pi = (long long)blockIdx.x * blockDim.x + threadIdx.x;
    if (pi >= npairs) return;

    u64 X0, X1;
    {
        float4 xx = reinterpret_cast<const float4*>(x)[pi];
        X0 = pk(xx.x, xx.z);   // coord 0 of point a, point b
        X1 = pk(xx.y, xx.w);   // coord 1
    }

    // ================= main net =================
    u64 m2v, magA, magD;
    {
        u64 h0[8];
        #pragma unroll
        for (int i = 0; i < 8; i++)
            h0[i] = elu2(fma2(X1, W0[i * 2 + 1], fma2(X0, W0[i * 2], B0[i])));

        u64 h1[8];
        #pragma unroll
        for (int i = 0; i < 8; i++) {
            u64 a0 = B1[i], a1 = 0ULL;
            #pragma unroll
            for (int j = 0; j < 8; j += 2) {
                a0 = fma2(h0[j],     W1[i * 8 + j],     a0);
                a1 = fma2(h0[j + 1], W1[i * 8 + j + 1], a1);
            }
            h1[i] = elu2(add2(a0, a1));
        }

        u64 bb[4];
        #pragma unroll
        for (int i = 0; i < 4; i++) {
            u64 a0 = B2[i], a1 = 0ULL;
            #pragma unroll
            for (int j = 0; j < 8; j += 2) {
                a0 = fma2(h1[j],     W2[i * 8 + j],     a0);
                a1 = fma2(h1[j + 1], W2[i * 8 + j + 1], a1);
            }
            bb[i] = add2(a0, a1);
        }
        m2v  = fma2(bb[0], bb[1], mul2(bb[2], bb[3]));
        magA = fma2(bb[0], bb[0], mul2(bb[2], bb[2]));
        magD = fma2(bb[1], bb[1], mul2(bb[3], bb[3]));
    }

    // ================= p nets (NV=2), forward + analytic backward =================
    u64 G0 = 0ULL, G1 = 0ULL;

    #pragma unroll
    for (int v = 0; v < 2; v++) {
        // f1 = tanh(x @ pW1^T + pb1)
        u64 f1[8];
        #pragma unroll
        for (int o = 0; o < 8; o++)
            f1[o] = tanh2(fma2(X1, PW1[v * 16 + o * 2 + 1],
                          fma2(X0, PW1[v * 16 + o * 2], PB1[v * 8 + o])));

        // f2 = tanh(f1 @ pW2^T + pb2)
        u64 f2[8];
        #pragma unroll
        for (int q = 0; q < 8; q++) {
            u64 a0 = PB2[v * 8 + q], a1 = 0ULL;
            #pragma unroll
            for (int pp = 0; pp < 8; pp += 2) {
                a0 = fma2(f1[pp],     PW2[v * 64 + q * 8 + pp],     a0);
                a1 = fma2(f1[pp + 1], PW2[v * 64 + q * 8 + pp + 1], a1);
            }
            f2[q] = tanh2(add2(a0, a1));
        }

        // z = f2 . pW3 + pb3 ; s = sigma(sigma(z)) ; ds = s(1-s)
        u64 DS;
        {
            u64 a0 = PB3[v], a1 = 0ULL;
            #pragma unroll
            for (int pp = 0; pp < 8; pp += 2) {
                a0 = fma2(f2[pp],     PW3[v * 8 + pp],     a0);
                a1 = fma2(f2[pp + 1], PW3[v * 8 + pp + 1], a1);
            }
            float za, zb; upk(add2(a0, a1), za, zb);
            float sa = sigmoid_fast(sigmoid_fast(za));
            float sb = sigmoid_fast(sigmoid_fast(zb));
            DS = pk(sa * (1.f - sa), sb * (1.f - sb));
        }

        // gq'_q = ds * pW3_q * (f2_q^2 - 1)   [= -gq; sign cancels below]
        #pragma unroll
        for (int q = 0; q < 8; q++) {
            u64 u2 = fma2(f2[q], f2[q], MONE2);     // f2^2 - 1
            f2[q] = mul2(mul2(DS, PW3[v * 8 + q]), u2);
        }

        // gp_p = (sum_q gq'_q * W2[q,p]) * (f1_p^2 - 1)  [two flips cancel]
        #pragma unroll
        for (int pp = 0; pp < 8; pp++) {
            u64 a0 = 0ULL, a1 = 0ULL;
            #pragma unroll
            for (int q = 0; q < 8; q += 2) {
                a0 = fma2(f2[q],     PW2[v * 64 + q * 8 + pp],       a0);
                a1 = fma2(f2[q + 1], PW2[v * 64 + (q + 1) * 8 + pp], a1);
            }
            u64 u1 = fma2(f1[pp], f1[pp], MONE2);   // f1^2 - 1
            u64 gpv = mul2(add2(a0, a1), u1);
            G0 = fma2(gpv, PW1[v * 16 + pp * 2],     G0);
            G1 = fma2(gpv, PW1[v * 16 + pp * 2 + 1], G1);
        }
    }

    // out0 = 0.5*(magA*G0 + m2*G1); out1 = 0.5*(m2*G0 + magD*G1)
    u64 o0 = mul2(HALF2, fma2(magA, G0, mul2(m2v, G1)));
    u64 o1 = mul2(HALF2, fma2(m2v, G0, mul2(magD, G1)));
    float a0, b0c, a1, b1c;
    upk(o0, a0, b0c);
    upk(o1, a1, b1c);
    reinterpret_cast<float4*>(out)[pi] = make_float4(a0, a1, b0c, b1c);
}

extern "C" void kernel_launch(void* const* d_in, const int* in_sizes, int n_in,
                              void* d_out, int out_size)
{
    const float* x   = (const float*)d_in[1];
    const float* mW0 = (const float*)d_in[2];
    const float* mb0 = (const float*)d_in[3];
    const float* mW1 = (const float*)d_in[4];
    const float* mb1 = (const float*)d_in[5];
    const float* mW2 = (const float*)d_in[6];
    const float* mb2 = (const float*)d_in[7];
    const float* pW1 = (const float*)d_in[8];
    const float* pb1 = (const float*)d_in[9];
    const float* pW2 = (const float*)d_in[10];
    const float* pb2 = (const float*)d_in[11];
    const float* pW3 = (const float*)d_in[12];
    const float* pb3 = (const float*)d_in[13];

    int B = in_sizes[1] / 2;       // x is (B, 2)
    int npairs = B / 2;
    int threads = 128;
    int blocks = (npairs + threads - 1) / threads;

    odefunc_kernel<<<blocks, threads>>>(x, mW0, mb0, mW1, mb1, mW2, mb2,
                                        pW1, pb1, pW2, pb2, pW3, pb3,
                                        (float*)d_out, npairs);
}

// round 5
// speedup vs baseline: 1.9647x; 1.4900x over previous
#include <cuda_runtime.h>
#include <cuda_bf16.h>

// ODEFunc: per-point fused MLP forward + analytic gradient.
// f32x2 packed math (2 points per lane), NPAIR=2 pair-slots per thread so each
// broadcast LDS.64 weight feeds 2 FFMA2s (R4 showed NPAIR=1 saturates the
// LDS/issue port: L1 71.6%, dur 109us). Natural 255 regs / 8 warps per SM
// (any cap spills: R2/R3). Split even/odd accumulators -> 8 independent FMA
// chains to cover RAW latency at low occupancy. (f^2-1) sign-cancellation
// removes all backward XORs.

using u64 = unsigned long long;

__device__ __forceinline__ u64 pk(float lo, float hi) {
    u64 r; asm("mov.b64 %0,{%1,%2};" : "=l"(r) : "f"(lo), "f"(hi)); return r;
}
__device__ __forceinline__ void upk(u64 v, float& lo, float& hi) {
    asm("mov.b64 {%0,%1},%2;" : "=f"(lo), "=f"(hi) : "l"(v));
}
__device__ __forceinline__ u64 fma2(u64 a, u64 b, u64 c) {
    u64 d; asm("fma.rn.f32x2 %0,%1,%2,%3;" : "=l"(d) : "l"(a), "l"(b), "l"(c)); return d;
}
__device__ __forceinline__ u64 mul2(u64 a, u64 b) {
    u64 d; asm("mul.rn.f32x2 %0,%1,%2;" : "=l"(d) : "l"(a), "l"(b)); return d;
}
__device__ __forceinline__ u64 add2(u64 a, u64 b) {
    u64 d; asm("add.rn.f32x2 %0,%1,%2;" : "=l"(d) : "l"(a), "l"(b)); return d;
}

#define MONE2 0xBF800000BF800000ULL  // (-1.0f, -1.0f)
#define HALF2 0x3F0000003F000000ULL  // ( 0.5f,  0.5f)

__device__ __forceinline__ float tanh_fast(float x) {
    float r; asm("tanh.approx.f32 %0,%1;" : "=f"(r) : "f"(x)); return r;
}
__device__ __forceinline__ float exp_fast(float x) {
    float r; asm("ex2.approx.f32 %0,%1;" : "=f"(r) : "f"(x * 1.4426950408889634f)); return r;
}
__device__ __forceinline__ float sigmoid_fast(float x) {
    return fmaf(0.5f, tanh_fast(0.5f * x), 0.5f);
}
__device__ __forceinline__ u64 tanh2(u64 v) {
    float a, b; upk(v, a, b);
    return pk(tanh_fast(a), tanh_fast(b));
}
__device__ __forceinline__ u64 elu2(u64 v) {
    float a, b; upk(v, a, b);
    a = a > 0.f ? a : (exp_fast(a) - 1.f);
    b = b > 0.f ? b : (exp_fast(b) - 1.f);
    return pk(a, b);
}

#define NPAIR 2

__global__ void __launch_bounds__(128, 2)
odefunc_kernel(const float* __restrict__ x,
               const float* __restrict__ mW0, const float* __restrict__ mb0,
               const float* __restrict__ mW1, const float* __restrict__ mb1,
               const float* __restrict__ mW2, const float* __restrict__ mb2,
               const float* __restrict__ pW1, const float* __restrict__ pb1,
               const float* __restrict__ pW2, const float* __restrict__ pb2,
               const float* __restrict__ pW3, const float* __restrict__ pb3,
               float* __restrict__ out, int npairs)
{
    // ---- weights -> shared, replicated into both f32x2 halves ----
    __shared__ u64 wsm[342];
    {
        const float* srcs[12] = {mW0, mb0, mW1, mb1, mW2, mb2,
                                 pW1, pb1, pW2, pb2, pW3, pb3};
        const int offs[13] = {0, 16, 24, 88, 96, 128, 132, 164, 180, 308, 324, 340, 342};
        for (int idx = threadIdx.x; idx < 342; idx += blockDim.x) {
            int seg = 0;
            #pragma unroll
            for (int s2 = 0; s2 < 12; s2++)
                if (idx >= offs[s2 + 1]) seg = s2 + 1;
            float w = srcs[seg][idx - offs[seg]];
            wsm[idx] = pk(w, w);
        }
    }
    __syncthreads();

    const u64* W0  = wsm;         // 16 : [i*2+j]
    const u64* B0  = wsm + 16;    // 8
    const u64* W1  = wsm + 24;    // 64 : [i*8+j]
    const u64* B1  = wsm + 88;    // 8
    const u64* W2  = wsm + 96;    // 32 : [i*8+j]
    const u64* B2  = wsm + 128;   // 4
    const u64* PW1 = wsm + 132;   // 32 : [v*16+o*2+i]
    const u64* PB1 = wsm + 164;   // 16 : [v*8+o]
    const u64* PW2 = wsm + 180;   // 128: [v*64+q*8+p]
    const u64* PB2 = wsm + 308;   // 16 : [v*8+q]
    const u64* PW3 = wsm + 324;   // 16 : [v*8+p]
    const u64* PB3 = wsm + 340;   // 2  : [v]

    const long long base   = (long long)blockIdx.x * blockDim.x + threadIdx.x;
    const long long stride = (long long)gridDim.x * blockDim.x;

    long long pi[NPAIR];
    bool valid[NPAIR];
    u64 X0[NPAIR], X1[NPAIR];
    #pragma unroll
    for (int p = 0; p < NPAIR; p++) {
        pi[p] = base + (long long)p * stride;
        valid[p] = pi[p] < npairs;
        if (valid[p]) {
            float4 xx = reinterpret_cast<const float4*>(x)[pi[p]];
            X0[p] = pk(xx.x, xx.z);
            X1[p] = pk(xx.y, xx.w);
        } else {
            X0[p] = 0ULL; X1[p] = 0ULL;
        }
    }

    // ================= main net =================
    u64 m2v[NPAIR], magA[NPAIR], magD[NPAIR];
    {
        u64 h0[NPAIR][8];
        #pragma unroll
        for (int i = 0; i < 8; i++) {
            u64 w0 = W0[i * 2], w1 = W0[i * 2 + 1], b = B0[i];
            #pragma unroll
            for (int p = 0; p < NPAIR; p++)
                h0[p][i] = elu2(fma2(X1[p], w1, fma2(X0[p], w0, b)));
        }
        u64 h1[NPAIR][8];
        #pragma unroll
        for (int i = 0; i < 8; i++) {
            u64 a0[NPAIR], a1[NPAIR];
            u64 b = B1[i];
            #pragma unroll
            for (int p = 0; p < NPAIR; p++) { a0[p] = b; a1[p] = 0ULL; }
            #pragma unroll
            for (int j = 0; j < 8; j += 2) {
                u64 we = W1[i * 8 + j], wo = W1[i * 8 + j + 1];
                #pragma unroll
                for (int p = 0; p < NPAIR; p++) {
                    a0[p] = fma2(h0[p][j],     we, a0[p]);
                    a1[p] = fma2(h0[p][j + 1], wo, a1[p]);
                }
            }
            #pragma unroll
            for (int p = 0; p < NPAIR; p++) h1[p][i] = elu2(add2(a0[p], a1[p]));
        }
        u64 bb[NPAIR][4];
        #pragma unroll
        for (int i = 0; i < 4; i++) {
            u64 a0[NPAIR], a1[NPAIR];
            u64 b = B2[i];
            #pragma unroll
            for (int p = 0; p < NPAIR; p++) { a0[p] = b; a1[p] = 0ULL; }
            #pragma unroll
            for (int j = 0; j < 8; j += 2) {
                u64 we = W2[i * 8 + j], wo = W2[i * 8 + j + 1];
                #pragma unroll
                for (int p = 0; p < NPAIR; p++) {
                    a0[p] = fma2(h1[p][j],     we, a0[p]);
                    a1[p] = fma2(h1[p][j + 1], wo, a1[p]);
                }
            }
            #pragma unroll
            for (int p = 0; p < NPAIR; p++) bb[p][i] = add2(a0[p], a1[p]);
        }
        #pragma unroll
        for (int p = 0; p < NPAIR; p++) {
            m2v[p]  = fma2(bb[p][0], bb[p][1], mul2(bb[p][2], bb[p][3]));
            magA[p] = fma2(bb[p][0], bb[p][0], mul2(bb[p][2], bb[p][2]));
            magD[p] = fma2(bb[p][1], bb[p][1], mul2(bb[p][3], bb[p][3]));
        }
    }

    // ================= p nets (NV=2), forward + analytic backward =================
    u64 G0[NPAIR], G1[NPAIR];
    #pragma unroll
    for (int p = 0; p < NPAIR; p++) { G0[p] = 0ULL; G1[p] = 0ULL; }

    #pragma unroll
    for (int v = 0; v < 2; v++) {
        u64 f1[NPAIR][8];
        #pragma unroll
        for (int o = 0; o < 8; o++) {
            u64 w0 = PW1[v * 16 + o * 2], w1 = PW1[v * 16 + o * 2 + 1], b = PB1[v * 8 + o];
            #pragma unroll
            for (int p = 0; p < NPAIR; p++)
                f1[p][o] = tanh2(fma2(X1[p], w1, fma2(X0[p], w0, b)));
        }
        u64 f2[NPAIR][8];
        #pragma unroll
        for (int q = 0; q < 8; q++) {
            u64 a0[NPAIR], a1[NPAIR];
            u64 b = PB2[v * 8 + q];
            #pragma unroll
            for (int p = 0; p < NPAIR; p++) { a0[p] = b; a1[p] = 0ULL; }
            #pragma unroll
            for (int pp = 0; pp < 8; pp += 2) {
                u64 we = PW2[v * 64 + q * 8 + pp], wo = PW2[v * 64 + q * 8 + pp + 1];
                #pragma unroll
                for (int p = 0; p < NPAIR; p++) {
                    a0[p] = fma2(f1[p][pp],     we, a0[p]);
                    a1[p] = fma2(f1[p][pp + 1], wo, a1[p]);
                }
            }
            #pragma unroll
            for (int p = 0; p < NPAIR; p++) f2[p][q] = tanh2(add2(a0[p], a1[p]));
        }
        // z = f2 . pW3 + pb3 ; s = sigma(sigma(z)) ; ds = s(1-s)
        u64 DS[NPAIR];
        {
            u64 a0[NPAIR], a1[NPAIR];
            u64 b = PB3[v];
            #pragma unroll
            for (int p = 0; p < NPAIR; p++) { a0[p] = b; a1[p] = 0ULL; }
            #pragma unroll
            for (int pp = 0; pp < 8; pp += 2) {
                u64 we = PW3[v * 8 + pp], wo = PW3[v * 8 + pp + 1];
                #pragma unroll
                for (int p = 0; p < NPAIR; p++) {
                    a0[p] = fma2(f2[p][pp],     we, a0[p]);
                    a1[p] = fma2(f2[p][pp + 1], wo, a1[p]);
                }
            }
            #pragma unroll
            for (int p = 0; p < NPAIR; p++) {
                float za, zb; upk(add2(a0[p], a1[p]), za, zb);
                float sa = sigmoid_fast(sigmoid_fast(za));
                float sb = sigmoid_fast(sigmoid_fast(zb));
                DS[p] = pk(sa * (1.f - sa), sb * (1.f - sb));
            }
        }
        // gq'_q = ds * pW3_q * (f2_q^2 - 1)   (in place; sign cancels below)
        #pragma unroll
        for (int q = 0; q < 8; q++) {
            u64 w3 = PW3[v * 8 + q];
            #pragma unroll
            for (int p = 0; p < NPAIR; p++) {
                u64 u2 = fma2(f2[p][q], f2[p][q], MONE2);
                f2[p][q] = mul2(mul2(DS[p], w3), u2);
            }
        }
        // gp_p = (sum_q gq'_q * W2[q,p]) * (f1_p^2 - 1) ; G += gp_p * pW1[p,:]
        #pragma unroll
        for (int pp = 0; pp < 8; pp++) {
            u64 a0[NPAIR], a1[NPAIR];
            #pragma unroll
            for (int p = 0; p < NPAIR; p++) { a0[p] = 0ULL; a1[p] = 0ULL; }
            #pragma unroll
            for (int q = 0; q < 8; q += 2) {
                u64 we = PW2[v * 64 + q * 8 + pp], wo = PW2[v * 64 + (q + 1) * 8 + pp];
                #pragma unroll
                for (int p = 0; p < NPAIR; p++) {
                    a0[p] = fma2(f2[p][q],     we, a0[p]);
                    a1[p] = fma2(f2[p][q + 1], wo, a1[p]);
                }
            }
            u64 w0 = PW1[v * 16 + pp * 2], w1 = PW1[v * 16 + pp * 2 + 1];
            #pragma unroll
            for (int p = 0; p < NPAIR; p++) {
                u64 u1 = fma2(f1[p][pp], f1[p][pp], MONE2);
                u64 gpv = mul2(add2(a0[p], a1[p]), u1);
                G0[p] = fma2(gpv, w0, G0[p]);
                G1[p] = fma2(gpv, w1, G1[p]);
            }
        }
    }

    // out0 = 0.5*(magA*G0 + m2*G1); out1 = 0.5*(m2*G0 + magD*G1)
    #pragma unroll
    for (int p = 0; p < NPAIR; p++) {
        if (!valid[p]) continue;
        u64 o0 = mul2(HALF2, fma2(magA[p], G0[p], mul2(m2v[p], G1[p])));
        u64 o1 = mul2(HALF2, fma2(m2v[p], G0[p], mul2(magD[p], G1[p])));
        float a0, b0c, a1, b1c;
        upk(o0, a0, b0c);
        upk(o1, a1, b1c);
        reinterpret_cast<float4*>(out)[pi[p]] = make_float4(a0, a1, b0c, b1c);
    }
}

extern "C" void kernel_launch(void* const* d_in, const int* in_sizes, int n_in,
                              void* d_out, int out_size)
{
    const float* x   = (const float*)d_in[1];
    const float* mW0 = (const float*)d_in[2];
    const float* mb0 = (const float*)d_in[3];
    const float* mW1 = (const float*)d_in[4];
    const float* mb1 = (const float*)d_in[5];
    const float* mW2 = (const float*)d_in[6];
    const float* mb2 = (const float*)d_in[7];
    const float* pW1 = (const float*)d_in[8];
    const float* pb1 = (const float*)d_in[9];
    const float* pW2 = (const float*)d_in[10];
    const float* pb2 = (const float*)d_in[11];
    const float* pW3 = (const float*)d_in[12];
    const float* pb3 = (const float*)d_in[13];

    int B = in_sizes[1] / 2;       // x is (B, 2)
    int npairs = B / 2;
    int threads = 128;
    long long tot_threads = (npairs + NPAIR - 1) / NPAIR;
    int blocks = (int)((tot_threads + threads - 1) / threads);

    odefunc_kernel<<<blocks, threads>>>(x, mW0, mb0, mW1, mb1, mW2, mb2,
                                        pW1, pb1, pW2, pb2, pW3, pb3,
                                        (float*)d_out, npairs);
}